// round 15
// baseline (speedup 1.0000x reference)
#include <cuda_runtime.h>
#include <math.h>

// ---------------------------------------------------------------------------
// DenseCRFLoss on GB300.
//   out = WEIGHT * ( -(1/N) * sum_n sum_{i,j} exp(-0.5*d2_ij) * <s_i, s_j> )
// with d2 from 5-dim features [x/50, y/50, rgb/0.15] on the 64x64 downsampled
// grid, s = (2x2-avg bilinear downsample of seg) * nearest(ROI).
// Upper-triangle-only pair evaluation (x2 folded into final constant).
// ---------------------------------------------------------------------------

#define NIMG 4
#define CCH  3
#define KCLS 21
#define HIN  128
#define WIN  128
#define OH   64
#define OW   64
#define PPIX 4096            // OH*OW
#define REC  32              // floats per packed pixel record (128 B)
#define TRI_UNITS 528        // sum_{b=0..31} (32-b)
#define TOTAL_UNITS (NIMG * TRI_UNITS)

__device__ float g_packed[(size_t)NIMG * PPIX * REC];   // 2 MB scratch
__device__ float g_partials[TOTAL_UNITS];

// packed f32x2 FMA (Blackwell FFMA2): 2 fp32 FMAs per instruction
__device__ __forceinline__ float2 ffma2(float2 a, float2 b, float2 c) {
    unsigned long long ra = *reinterpret_cast<unsigned long long*>(&a);
    unsigned long long rb = *reinterpret_cast<unsigned long long*>(&b);
    unsigned long long rc = *reinterpret_cast<unsigned long long*>(&c);
    unsigned long long rd;
    asm("fma.rn.f32x2 %0, %1, %2, %3;" : "=l"(rd) : "l"(ra), "l"(rb), "l"(rc));
    return *reinterpret_cast<float2*>(&rd);
}

// ---------------------------------------------------------------------------
// Kernel 1: build packed per-pixel records.
//   rec[0..20]  = seg (2x2 average == bilinear at scale 0.5) * ROI(nearest)
//   rec[21..23] = 0 (padding so the 21-dot can run as 12 packed FMAs)
//   rec[24..28] = [x/50, y/50, r/0.15, g/0.15, b/0.15]
//   rec[29]     = ||feat||^2 ; rec[30..31] = 0
// ---------------------------------------------------------------------------
__global__ void precompute_kernel(const float* __restrict__ images,
                                  const float* __restrict__ segs,
                                  const float* __restrict__ rois)
{
    int idx = blockIdx.x * blockDim.x + threadIdx.x;
    if (idx >= NIMG * PPIX) return;
    int n = idx >> 12;
    int p = idx & 4095;
    int y = p >> 6, x = p & 63;
    int iy = y << 1, ix = x << 1;

    const float* img = images + ((size_t)n * CCH * HIN + iy) * WIN + ix;
    float r = img[0];
    float g = img[(size_t)HIN * WIN];
    float b = img[(size_t)2 * HIN * WIN];
    float roi = rois[((size_t)n * HIN + iy) * WIN + ix];

    float fx = (float)x / 50.0f;     // SIGMA_XY * SCALE = 50
    float fy = (float)y / 50.0f;
    float fr = r / 0.15f, fg = g / 0.15f, fb = b / 0.15f;
    float sq = fx * fx + fy * fy + fr * fr + fg * fg + fb * fb;

    float* rec = g_packed + (size_t)idx * REC;
    const float* sbase = segs + ((size_t)(n * KCLS) * HIN + iy) * WIN + ix;
#pragma unroll
    for (int k = 0; k < KCLS; k++) {
        const float* sp = sbase + (size_t)k * HIN * WIN;
        rec[k] = 0.25f * ((sp[0] + sp[1]) + (sp[WIN] + sp[WIN + 1])) * roi;
    }
    rec[21] = 0.f; rec[22] = 0.f; rec[23] = 0.f;
    rec[24] = fx;  rec[25] = fy;  rec[26] = fr; rec[27] = fg; rec[28] = fb;
    rec[29] = sq;  rec[30] = 0.f; rec[31] = 0.f;
}

// ---------------------------------------------------------------------------
// Kernel 2: one CTA per 128x128 upper-triangular tile.
//   thread t owns pixel i = I0 + t (record in registers),
//   j-tile staged in SMEM (16 KB), inner loop warp-broadcast LDS.
// DIAG tiles apply the {0, 0.5, 1} mask; off-diag tiles are mask-free.
// ---------------------------------------------------------------------------
template <bool DIAG>
__device__ __forceinline__ float pair_loop(const float* __restrict__ sj,
                                           const float2* __restrict__ si2,
                                           float2 fi0, float2 fi1,
                                           float fi4, float sqi,
                                           int ig, int J0)
{
    float acc = 0.f;
#pragma unroll 2
    for (int j = 0; j < 128; j++) {
        const float* rec = sj + j * REC;
        // --- d2 = max(sqi + sqj - 2 * <fi, fj>, 0) ---
        float2 f0  = *(const float2*)(rec + 24);
        float2 f1  = *(const float2*)(rec + 26);
        float  f4  = rec[28];
        float  sqj = rec[29];
        float2 dp  = ffma2(fi0, f0, make_float2(0.f, 0.f));
        dp         = ffma2(fi1, f1, dp);
        float dot5 = fmaf(fi4, f4, dp.x + dp.y);
        float d2   = fmaxf(fmaf(-2.f, dot5, sqi + sqj), 0.f);
        float w    = __expf(-0.5f * d2);           // FMUL + MUFU.EX2
        // --- g = <s_i, s_j> over 21 classes (12 packed FMAs, zero-padded) ---
        const float2* sj2 = (const float2*)rec;
        float2 ga = ffma2(si2[0], sj2[0], make_float2(0.f, 0.f));
        float2 gb = ffma2(si2[1], sj2[1], make_float2(0.f, 0.f));
#pragma unroll
        for (int q = 2; q < 12; q += 2) {
            ga = ffma2(si2[q],     sj2[q],     ga);
            gb = ffma2(si2[q + 1], sj2[q + 1], gb);
        }
        float g = (ga.x + ga.y) + (gb.x + gb.y);
        if (DIAG) {
            int jg = J0 + j;
            float m = (jg > ig) ? 1.0f : ((jg == ig) ? 0.5f : 0.0f);
            w *= m;
        }
        acc = fmaf(w, g, acc);
    }
    return acc;
}

__global__ void __launch_bounds__(128) pairs_kernel()
{
    __shared__ float sj[128 * REC];
    __shared__ float wred[4];

    // map blockIdx.x -> (n, ib, js) over the upper triangle (js >= ib)
    int c = blockIdx.x;
    int n = c / TRI_UNITS;
    int r = c - n * TRI_UNITS;
    int u = TRI_UNITS - 1 - r;
    int rowq = (int)floorf((sqrtf(8.f * (float)u + 1.f) - 1.f) * 0.5f);
    while ((rowq + 1) * (rowq + 2) / 2 <= u) rowq++;
    while (rowq * (rowq + 1) / 2 > u) rowq--;
    int ib = 31 - rowq;
    int js = 31 - (u - rowq * (rowq + 1) / 2);
    int I0 = ib << 7, J0 = js << 7;

    int tid = threadIdx.x;
    int ig  = I0 + tid;

    // load this thread's i-record into registers
    const float* irec = g_packed + ((size_t)n * PPIX + ig) * REC;
    float2 si2[12];
#pragma unroll
    for (int q = 0; q < 12; q++) si2[q] = *(const float2*)(irec + 2 * q);
    float2 fi0 = *(const float2*)(irec + 24);
    float2 fi1 = *(const float2*)(irec + 26);
    float  fi4 = irec[28];
    float  sqi = irec[29];

    // cooperative stage of the j-tile (128 records = 16 KB), coalesced float4
    const float4* src = (const float4*)(g_packed + ((size_t)n * PPIX + J0) * REC);
    float4* dst = (float4*)sj;
#pragma unroll
    for (int q = 0; q < 8; q++) dst[tid + 128 * q] = src[tid + 128 * q];
    __syncthreads();

    float acc = (ib == js)
        ? pair_loop<true >(sj, si2, fi0, fi1, fi4, sqi, ig, J0)
        : pair_loop<false>(sj, si2, fi0, fi1, fi4, sqi, ig, J0);

    // deterministic CTA reduction
#pragma unroll
    for (int o = 16; o > 0; o >>= 1)
        acc += __shfl_down_sync(0xffffffffu, acc, o);
    if ((tid & 31) == 0) wred[tid >> 5] = acc;
    __syncthreads();
    if (tid == 0)
        g_partials[blockIdx.x] = (wred[0] + wred[1]) + (wred[2] + wred[3]);
}

// ---------------------------------------------------------------------------
// Kernel 3: deterministic tree-sum of partials; apply constants.
//   Sum_full = 2*A (triangle doubling);  out = WEIGHT * (-Sum_full / N)
//            = (-2 * 2e-9 / 4) * A = -1e-9 * A
// ---------------------------------------------------------------------------
__global__ void finalize_kernel(float* __restrict__ out)
{
    __shared__ float sm[256];
    int t = threadIdx.x;
    float v = 0.f;
    for (int i = t; i < TOTAL_UNITS; i += 256) v += g_partials[i];
    sm[t] = v;
    __syncthreads();
#pragma unroll
    for (int s = 128; s > 0; s >>= 1) {
        if (t < s) sm[t] += sm[t + s];
        __syncthreads();
    }
    if (t == 0) out[0] = -1e-9f * sm[0];
}

extern "C" void kernel_launch(void* const* d_in, const int* in_sizes, int n_in,
                              void* d_out, int out_size)
{
    const float* images = (const float*)d_in[0];
    const float* segs   = (const float*)d_in[1];
    const float* rois   = (const float*)d_in[2];
    float* out = (float*)d_out;

    precompute_kernel<<<(NIMG * PPIX + 255) / 256, 256>>>(images, segs, rois);
    pairs_kernel<<<TOTAL_UNITS, 128>>>();
    finalize_kernel<<<1, 256>>>(out);
}

// round 16
// speedup vs baseline: 1.0138x; 1.0138x over previous
#include <cuda_runtime.h>
#include <math.h>

// ---------------------------------------------------------------------------
// DenseCRFLoss on GB300.
//   out = WEIGHT * ( -(1/N) * sum_n sum_{i,j} exp(-0.5*d2_ij) * <s_i, s_j> )
// with d2 from 5-dim features [x/50, y/50, rgb/0.15] on the 64x64 downsampled
// grid, s = (2x2-avg bilinear downsample of seg) * nearest(ROI).
// Upper-triangle-only pair evaluation (x2 folded into final constant).
// ---------------------------------------------------------------------------

#define NIMG 4
#define CCH  3
#define KCLS 21
#define HIN  128
#define WIN  128
#define OH   64
#define OW   64
#define PPIX 4096            // OH*OW
#define REC  32              // floats per packed pixel record (128 B)
#define TRI_UNITS 528        // sum_{b=0..31} (32-b)
#define TOTAL_UNITS (NIMG * TRI_UNITS)

__device__ float g_packed[(size_t)NIMG * PPIX * REC];   // 2 MB scratch
__device__ float g_partials[TOTAL_UNITS];

// packed f32x2 FMA (Blackwell FFMA2): 2 fp32 FMAs per instruction
__device__ __forceinline__ float2 ffma2(float2 a, float2 b, float2 c) {
    unsigned long long ra = *reinterpret_cast<unsigned long long*>(&a);
    unsigned long long rb = *reinterpret_cast<unsigned long long*>(&b);
    unsigned long long rc = *reinterpret_cast<unsigned long long*>(&c);
    unsigned long long rd;
    asm("fma.rn.f32x2 %0, %1, %2, %3;" : "=l"(rd) : "l"(ra), "l"(rb), "l"(rc));
    return *reinterpret_cast<float2*>(&rd);
}

// ---------------------------------------------------------------------------
// Kernel 1: build packed per-pixel records.
//   rec[0..20]  = seg (2x2 average == bilinear at scale 0.5) * ROI(nearest)
//   rec[21..23] = 0 (padding so the 21-dot can run as 12 packed FMAs)
//   rec[24..28] = [x/50, y/50, r/0.15, g/0.15, b/0.15]
//   rec[29]     = ||feat||^2 ; rec[30..31] = 0
// ---------------------------------------------------------------------------
__global__ void precompute_kernel(const float* __restrict__ images,
                                  const float* __restrict__ segs,
                                  const float* __restrict__ rois)
{
    int idx = blockIdx.x * blockDim.x + threadIdx.x;
    if (idx >= NIMG * PPIX) return;
    int n = idx >> 12;
    int p = idx & 4095;
    int y = p >> 6, x = p & 63;
    int iy = y << 1, ix = x << 1;

    const float* img = images + ((size_t)n * CCH * HIN + iy) * WIN + ix;
    float r = img[0];
    float g = img[(size_t)HIN * WIN];
    float b = img[(size_t)2 * HIN * WIN];
    float roi = rois[((size_t)n * HIN + iy) * WIN + ix];

    float fx = (float)x / 50.0f;     // SIGMA_XY * SCALE = 50
    float fy = (float)y / 50.0f;
    float fr = r / 0.15f, fg = g / 0.15f, fb = b / 0.15f;
    float sq = fx * fx + fy * fy + fr * fr + fg * fg + fb * fb;

    float* rec = g_packed + (size_t)idx * REC;
    const float* sbase = segs + ((size_t)(n * KCLS) * HIN + iy) * WIN + ix;
#pragma unroll
    for (int k = 0; k < KCLS; k++) {
        const float* sp = sbase + (size_t)k * HIN * WIN;
        rec[k] = 0.25f * ((sp[0] + sp[1]) + (sp[WIN] + sp[WIN + 1])) * roi;
    }
    rec[21] = 0.f; rec[22] = 0.f; rec[23] = 0.f;
    rec[24] = fx;  rec[25] = fy;  rec[26] = fr; rec[27] = fg; rec[28] = fb;
    rec[29] = sq;  rec[30] = 0.f; rec[31] = 0.f;
}

// ---------------------------------------------------------------------------
// Kernel 2: one CTA per 128x128 upper-triangular tile.
//   thread t owns pixel i = I0 + t (record in registers),
//   j-tile staged in SMEM (16 KB), inner loop warp-broadcast LDS.
// DIAG tiles apply the {0, 0.5, 1} mask; off-diag tiles are mask-free.
// ---------------------------------------------------------------------------
template <bool DIAG>
__device__ __forceinline__ float pair_loop(const float* __restrict__ sj,
                                           const float2* __restrict__ si2,
                                           float2 fi0, float2 fi1,
                                           float fi4, float sqi,
                                           int ig, int J0)
{
    float acc = 0.f;
#pragma unroll 2
    for (int j = 0; j < 128; j++) {
        const float* rec = sj + j * REC;
        // --- d2 = max(sqi + sqj - 2 * <fi, fj>, 0) ---
        float2 f0  = *(const float2*)(rec + 24);
        float2 f1  = *(const float2*)(rec + 26);
        float  f4  = rec[28];
        float  sqj = rec[29];
        float2 dp  = ffma2(fi0, f0, make_float2(0.f, 0.f));
        dp         = ffma2(fi1, f1, dp);
        float dot5 = fmaf(fi4, f4, dp.x + dp.y);
        float d2   = fmaxf(fmaf(-2.f, dot5, sqi + sqj), 0.f);
        float w    = __expf(-0.5f * d2);           // FMUL + MUFU.EX2
        // --- g = <s_i, s_j> over 21 classes (12 packed FMAs, zero-padded) ---
        const float2* sj2 = (const float2*)rec;
        float2 ga = ffma2(si2[0], sj2[0], make_float2(0.f, 0.f));
        float2 gb = ffma2(si2[1], sj2[1], make_float2(0.f, 0.f));
#pragma unroll
        for (int q = 2; q < 12; q += 2) {
            ga = ffma2(si2[q],     sj2[q],     ga);
            gb = ffma2(si2[q + 1], sj2[q + 1], gb);
        }
        float g = (ga.x + ga.y) + (gb.x + gb.y);
        if (DIAG) {
            int jg = J0 + j;
            float m = (jg > ig) ? 1.0f : ((jg == ig) ? 0.5f : 0.0f);
            w *= m;
        }
        acc = fmaf(w, g, acc);
    }
    return acc;
}

__global__ void __launch_bounds__(128) pairs_kernel()
{
    __shared__ float sj[128 * REC];
    __shared__ float wred[4];

    // map blockIdx.x -> (n, ib, js) over the upper triangle (js >= ib)
    int c = blockIdx.x;
    int n = c / TRI_UNITS;
    int r = c - n * TRI_UNITS;
    int u = TRI_UNITS - 1 - r;
    int rowq = (int)floorf((sqrtf(8.f * (float)u + 1.f) - 1.f) * 0.5f);
    while ((rowq + 1) * (rowq + 2) / 2 <= u) rowq++;
    while (rowq * (rowq + 1) / 2 > u) rowq--;
    int ib = 31 - rowq;
    int js = 31 - (u - rowq * (rowq + 1) / 2);
    int I0 = ib << 7, J0 = js << 7;

    int tid = threadIdx.x;
    int ig  = I0 + tid;

    // load this thread's i-record into registers
    const float* irec = g_packed + ((size_t)n * PPIX + ig) * REC;
    float2 si2[12];
#pragma unroll
    for (int q = 0; q < 12; q++) si2[q] = *(const float2*)(irec + 2 * q);
    float2 fi0 = *(const float2*)(irec + 24);
    float2 fi1 = *(const float2*)(irec + 26);
    float  fi4 = irec[28];
    float  sqi = irec[29];

    // cooperative stage of the j-tile (128 records = 16 KB), coalesced float4
    const float4* src = (const float4*)(g_packed + ((size_t)n * PPIX + J0) * REC);
    float4* dst = (float4*)sj;
#pragma unroll
    for (int q = 0; q < 8; q++) dst[tid + 128 * q] = src[tid + 128 * q];
    __syncthreads();

    float acc = (ib == js)
        ? pair_loop<true >(sj, si2, fi0, fi1, fi4, sqi, ig, J0)
        : pair_loop<false>(sj, si2, fi0, fi1, fi4, sqi, ig, J0);

    // deterministic CTA reduction
#pragma unroll
    for (int o = 16; o > 0; o >>= 1)
        acc += __shfl_down_sync(0xffffffffu, acc, o);
    if ((tid & 31) == 0) wred[tid >> 5] = acc;
    __syncthreads();
    if (tid == 0)
        g_partials[blockIdx.x] = (wred[0] + wred[1]) + (wred[2] + wred[3]);
}

// ---------------------------------------------------------------------------
// Kernel 3: deterministic tree-sum of partials; apply constants.
//   Sum_full = 2*A (triangle doubling);  out = WEIGHT * (-Sum_full / N)
//            = (-2 * 2e-9 / 4) * A = -1e-9 * A
// ---------------------------------------------------------------------------
__global__ void finalize_kernel(float* __restrict__ out)
{
    __shared__ float sm[256];
    int t = threadIdx.x;
    float v = 0.f;
    for (int i = t; i < TOTAL_UNITS; i += 256) v += g_partials[i];
    sm[t] = v;
    __syncthreads();
#pragma unroll
    for (int s = 128; s > 0; s >>= 1) {
        if (t < s) sm[t] += sm[t + s];
        __syncthreads();
    }
    if (t == 0) out[0] = -1e-9f * sm[0];
}

extern "C" void kernel_launch(void* const* d_in, const int* in_sizes, int n_in,
                              void* d_out, int out_size)
{
    const float* images = (const float*)d_in[0];
    const float* segs   = (const float*)d_in[1];
    const float* rois   = (const float*)d_in[2];
    float* out = (float*)d_out;

    precompute_kernel<<<(NIMG * PPIX + 255) / 256, 256>>>(images, segs, rois);
    pairs_kernel<<<TOTAL_UNITS, 128>>>();
    finalize_kernel<<<1, 256>>>(out);
}